// round 3
// baseline (speedup 1.0000x reference)
#include <cuda_runtime.h>
#include <math.h>

#define BB 16
#define TT 4096
#define DD 512
#define NLEV 3
#define CHUNK 512
#define NCHUNK (TT/CHUNK)   // 8
#define NECH 4              // e-chunks in k_proj

// ---------------- device scratch (no allocations allowed) ----------------
__device__ float g_u_part[NECH][NLEV][BB][DD];   // partial u = s_prev @ Vw
__device__ float g_c_part[NECH][NLEV][BB];       // partial c = s_prev . Vb
__device__ float g_u[NLEV][BB][DD];
__device__ float g_c[NLEV][BB];
__device__ float g_dots[NLEV][BB][TT];           // enc_hs . u_i per token
__device__ float g_att[NLEV][BB][TT];            // normalized attention (zero-padded)
__device__ float g_pooled_part[NCHUNK][NLEV][BB][DD];
__device__ float g_ctx_part[NLEV][NCHUNK][BB][DD];

// ---------------- kernel 1: u_i = s_prev @ Vw[i], c_i = s_prev . Vb[i] ----
// grid (16,3): x = dtile(0..3) | echunk(0..3)<<2 ; block 128
__global__ void k_proj(const float* __restrict__ s_prev,
                       const float* __restrict__ Vw,
                       const float* __restrict__ Vb) {
    int i  = blockIdx.y;
    int dt = blockIdx.x & 3;
    int ec = blockIdx.x >> 2;
    int d  = dt * 128 + threadIdx.x;
    int e0 = ec * 128;

    __shared__ float sp[BB][128];
    for (int idx = threadIdx.x; idx < BB * 128; idx += 128) {
        int b = idx >> 7, e = idx & 127;
        sp[b][e] = s_prev[b * DD + e0 + e];
    }
    __syncthreads();

    float acc[BB];
#pragma unroll
    for (int b = 0; b < BB; b++) acc[b] = 0.f;

    const float* wp = Vw + (size_t)i * DD * DD + (size_t)e0 * DD + d;
#pragma unroll 4
    for (int e = 0; e < 128; e++) {
        float w = wp[(size_t)e * DD];
#pragma unroll
        for (int b = 0; b < BB; b++) acc[b] = fmaf(sp[b][e], w, acc[b]);
    }
#pragma unroll
    for (int b = 0; b < BB; b++) g_u_part[ec][i][b][d] = acc[b];

    if (dt == 0 && threadIdx.x < BB) {
        int b = threadIdx.x;
        float c = 0.f;
        for (int e = 0; e < 128; e++) c = fmaf(sp[b][e], Vb[i * DD + e0 + e], c);
        g_c_part[ec][i][b] = c;
    }
}

// ---------------- kernel 2: fold partials ---------------------------------
__global__ void k_fold_u() {
    int idx = blockIdx.x * 256 + threadIdx.x;
    if (idx < NLEV * BB * DD) {
        float s = 0.f;
#pragma unroll
        for (int p = 0; p < NECH; p++) s += (&g_u_part[0][0][0][0])[p * NLEV * BB * DD + idx];
        (&g_u[0][0][0])[idx] = s;
    }
    if (idx < NLEV * BB) {
        float s = 0.f;
#pragma unroll
        for (int p = 0; p < NECH; p++) s += (&g_c_part[0][0][0])[p * NLEV * BB + idx];
        (&g_c[0][0])[idx] = s;
    }
}

// ---------------- kernel 3: dots_i[b,t] = enc_hs[b,t,:] . u_i[b,:] --------
// grid (T/32, B), 256 threads (8 warps, each warp does 4 rows)
__global__ void k_dots(const float* __restrict__ enc) {
    int b  = blockIdx.y;
    int t0 = blockIdx.x * 32;

    __shared__ __align__(16) float su[NLEV * DD];
    for (int idx = threadIdx.x; idx < NLEV * DD; idx += 256) {
        int i = idx / DD, d = idx % DD;
        su[idx] = g_u[i][b][d];
    }
    __syncthreads();

    int warp = threadIdx.x >> 5, lane = threadIdx.x & 31;
    const float4* u0 = (const float4*)(su);
    const float4* u1 = (const float4*)(su + DD);
    const float4* u2 = (const float4*)(su + 2 * DD);
    const float4* e4 = (const float4*)(enc + (size_t)b * TT * DD);

#pragma unroll
    for (int r = 0; r < 4; r++) {
        int t = t0 + r * 8 + warp;
        const float4* row = e4 + (size_t)t * (DD / 4);
        float a0 = 0.f, a1 = 0.f, a2 = 0.f;
#pragma unroll
        for (int q = 0; q < 4; q++) {
            float4 h  = row[lane + 32 * q];
            float4 v0 = u0[lane + 32 * q];
            float4 v1 = u1[lane + 32 * q];
            float4 v2 = u2[lane + 32 * q];
            a0 += h.x * v0.x + h.y * v0.y + h.z * v0.z + h.w * v0.w;
            a1 += h.x * v1.x + h.y * v1.y + h.z * v1.z + h.w * v1.w;
            a2 += h.x * v2.x + h.y * v2.y + h.z * v2.z + h.w * v2.w;
        }
#pragma unroll
        for (int off = 16; off; off >>= 1) {
            a0 += __shfl_down_sync(0xFFFFFFFFu, a0, off);
            a1 += __shfl_down_sync(0xFFFFFFFFu, a1, off);
            a2 += __shfl_down_sync(0xFFFFFFFFu, a2, off);
        }
        if (lane == 0) {
            g_dots[0][b][t] = a0;
            g_dots[1][b][t] = a1;
            g_dots[2][b][t] = a2;
        }
    }
}

// ---------------- kernel 4: window-sum logits + masked softmax ------------
// grid (3, B), 256 threads. Level i: k=i+1, L=T-k+1.
// Writes normalized attention (zero at masked / out-of-range positions).
__global__ void k_softmax(const int* __restrict__ mask, float* __restrict__ out_att) {
    int i = blockIdx.x, b = blockIdx.y;
    int k = i + 1, L = TT - i;

    __shared__ float s[TT];
    __shared__ float red[256];

    const float* dp = &g_dots[i][b][0];
    const int*   mp = mask + b * TT;
    float c     = g_c[i][b];
    float inv_k = 1.f / (float)k;

    float mx = -INFINITY;
    for (int l = threadIdx.x; l < TT; l += 256) {
        float v = -INFINITY;
        if (l < L) {
            float ws = 0.f;
            bool  m  = false;
            for (int j = 0; j < k; j++) { ws += dp[l + j]; m = m || (mp[l + j] != 0); }
            if (!m) v = ws * inv_k + c;
        }
        s[l] = v;
        mx = fmaxf(mx, v);
    }
    red[threadIdx.x] = mx;
    __syncthreads();
    for (int w = 128; w; w >>= 1) {
        if (threadIdx.x < w) red[threadIdx.x] = fmaxf(red[threadIdx.x], red[threadIdx.x + w]);
        __syncthreads();
    }
    mx = red[0];
    __syncthreads();

    float sum = 0.f;
    for (int l = threadIdx.x; l < TT; l += 256) {
        float v = s[l];
        float e = (v == -INFINITY) ? 0.f : __expf(v - mx);
        s[l] = e;
        sum += e;
    }
    red[threadIdx.x] = sum;
    __syncthreads();
    for (int w = 128; w; w >>= 1) {
        if (threadIdx.x < w) red[threadIdx.x] += red[threadIdx.x + w];
        __syncthreads();
    }
    float inv = 1.f / red[0];

    for (int l = threadIdx.x; l < TT; l += 256) {
        float a = s[l] * inv;
        g_att[i][b][l] = a;
        if (i == 0) out_att[b * TT + l] = a;
    }
}

// ---------------- kernel 5: pooled_i[b,d] = sum_t w_i[b,t] * enc[b,t,d] ---
// w_i[b,t] = (1/k) * sum_{j<k, t-j>=0} att_i[b,t-j]  (att zero-padded)
// grid (NCHUNK, B) -- chunks visited in REVERSE order for L2 reuse from k_dots.
__global__ void k_pooled(const float* __restrict__ enc) {
    int b     = blockIdx.y;
    int chunk = NCHUNK - 1 - blockIdx.x;
    int t0    = chunk * CHUNK;

    __shared__ float sw[NLEV][CHUNK];
    for (int j = threadIdx.x; j < CHUNK; j += 256) {
        int t = t0 + j;
        float w0 = g_att[0][b][t];
        float w1 = g_att[1][b][t];
        if (t >= 1) w1 += g_att[1][b][t - 1];
        float w2 = g_att[2][b][t];
        if (t >= 1) w2 += g_att[2][b][t - 1];
        if (t >= 2) w2 += g_att[2][b][t - 2];
        sw[0][j] = w0;
        sw[1][j] = w1 * 0.5f;
        sw[2][j] = w2 * (1.f / 3.f);
    }
    __syncthreads();

    int d0 = threadIdx.x, d1 = threadIdx.x + 256;
    float acc[NLEV][2];
#pragma unroll
    for (int i = 0; i < NLEV; i++) { acc[i][0] = 0.f; acc[i][1] = 0.f; }

    const float* base = enc + (size_t)b * TT * DD + (size_t)t0 * DD;
#pragma unroll 4
    for (int j = 0; j < CHUNK; j++) {
        float h0 = base[(size_t)j * DD + d0];
        float h1 = base[(size_t)j * DD + d1];
#pragma unroll
        for (int i = 0; i < NLEV; i++) {
            float w = sw[i][j];
            acc[i][0] = fmaf(w, h0, acc[i][0]);
            acc[i][1] = fmaf(w, h1, acc[i][1]);
        }
    }
#pragma unroll
    for (int i = 0; i < NLEV; i++) {
        g_pooled_part[chunk][i][b][d0] = acc[i][0];
        g_pooled_part[chunk][i][b][d1] = acc[i][1];
    }
}

// ---------------- kernel 6: ctx partials = pooled_i @ Ww[i]^T -------------
// grid (8 dchunks, 4 etiles, 3 levels), 128 threads
__global__ void k_ctx(const float* __restrict__ Ww) {
    int i  = blockIdx.z;
    int e0 = blockIdx.y * 128;
    int dc = blockIdx.x;
    int d0 = dc * 64;

    __shared__ float tW[128 * 65];   // padded to avoid bank conflicts
    __shared__ float sp[BB * 64];

    for (int idx = threadIdx.x; idx < 128 * 64; idx += 128) {
        int r = idx >> 6, c = idx & 63;
        tW[r * 65 + c] = Ww[(size_t)i * DD * DD + (size_t)(e0 + r) * DD + d0 + c];
    }
    for (int idx = threadIdx.x; idx < BB * 64; idx += 128) {
        int b = idx >> 6, c = idx & 63;
        float s = 0.f;
#pragma unroll
        for (int ch = 0; ch < NCHUNK; ch++) s += g_pooled_part[ch][i][b][d0 + c];
        sp[idx] = s;
    }
    __syncthreads();

    float acc[BB];
#pragma unroll
    for (int b = 0; b < BB; b++) acc[b] = 0.f;

    for (int c = 0; c < 64; c++) {
        float w = tW[threadIdx.x * 65 + c];
#pragma unroll
        for (int b = 0; b < BB; b++) acc[b] = fmaf(w, sp[b * 64 + c], acc[b]);
    }
    int e = e0 + threadIdx.x;
#pragma unroll
    for (int b = 0; b < BB; b++) g_ctx_part[i][dc][b][e] = acc[b];
}

// ---------------- kernel 7: final ctx fold + bias -> d_out ----------------
__global__ void k_out(const float* __restrict__ Wb, float* __restrict__ out_ctx) {
    int idx = blockIdx.x * 256 + threadIdx.x;  // 0 .. B*D-1
    if (idx >= BB * DD) return;
    int e = idx % DD;
    float s = 0.f;
#pragma unroll
    for (int i = 0; i < NLEV; i++) {
#pragma unroll
        for (int ch = 0; ch < NCHUNK; ch++) {
            s += (&g_ctx_part[0][0][0][0])[((i * NCHUNK + ch) * BB * DD) + idx];
        }
        s += Wb[i * DD + e];
    }
    out_ctx[idx] = s;
}

// ---------------- launch ---------------------------------------------------
extern "C" void kernel_launch(void* const* d_in, const int* in_sizes, int n_in,
                              void* d_out, int out_size) {
    const float* s_prev = (const float*)d_in[0];   // [B, D]
    const float* enc    = (const float*)d_in[1];   // [B, T, D]
    const int*   mask   = (const int*)  d_in[2];   // [B, T] (bool serialized 4B; !=0 == masked)
    const float* Vw     = (const float*)d_in[3];   // [N, D, D]
    const float* Vb     = (const float*)d_in[4];   // [N, D]
    const float* Ww     = (const float*)d_in[5];   // [N, D, D]
    const float* Wb     = (const float*)d_in[6];   // [N, D]

    float* out     = (float*)d_out;
    float* out_ctx = out;            // [B, D]  (tuple element 0)
    float* out_att = out + BB * DD;  // [B, T]  (tuple element 1)

    k_proj   <<<dim3(16, NLEV), 128>>>(s_prev, Vw, Vb);
    k_fold_u <<<(NLEV * BB * DD + 255) / 256, 256>>>();
    k_dots   <<<dim3(TT / 32, BB), 256>>>(enc);
    k_softmax<<<dim3(NLEV, BB), 256>>>(mask, out_att);
    k_pooled <<<dim3(NCHUNK, BB), 256>>>(enc);
    k_ctx    <<<dim3(8, 4, NLEV), 128>>>(Ww);
    k_out    <<<(BB * DD + 255) / 256, 256>>>(Wb, out_ctx);
}

// round 4
// speedup vs baseline: 1.3511x; 1.3511x over previous
#include <cuda_runtime.h>
#include <math.h>

#define BB 16
#define TT 4096
#define DD 512
#define NLEV 3
#define NECH 4              // e-chunks in k_proj
#define PCH 128             // tokens per pooled chunk
#define NPCH (TT/PCH)       // 32
#define CTXCH 8             // d-chunks in k_ctx

// ---------------- device scratch (no allocations allowed) ----------------
__device__ __align__(16) float g_u_part[NECH][NLEV][BB][DD];
__device__ float g_c_part[NECH][NLEV][BB];
__device__ __align__(16) float g_u[NLEV][BB][DD];
__device__ float g_dots[NLEV][BB][TT];
__device__ float g_w[NLEV][BB][TT];                     // combined pooling weights
__device__ __align__(16) float g_pooled_part[NPCH][NLEV][BB][DD];
__device__ float g_ctx_part[NLEV][CTXCH][BB][DD];

// ---------------- kernel 1: u_i = s_prev @ Vw[i], c_i = s_prev . Vb[i] ----
// grid (16,3): x = dtile(0..3) | echunk(0..3)<<2 ; block 128
__global__ void k_proj(const float* __restrict__ s_prev,
                       const float* __restrict__ Vw,
                       const float* __restrict__ Vb) {
    int i  = blockIdx.y;
    int dt = blockIdx.x & 3;
    int ec = blockIdx.x >> 2;
    int d  = dt * 128 + threadIdx.x;
    int e0 = ec * 128;

    __shared__ float sp[BB][128];
    for (int idx = threadIdx.x; idx < BB * 128; idx += 128) {
        int b = idx >> 7, e = idx & 127;
        sp[b][e] = s_prev[b * DD + e0 + e];
    }
    __syncthreads();

    float acc[BB];
#pragma unroll
    for (int b = 0; b < BB; b++) acc[b] = 0.f;

    const float* wp = Vw + (size_t)i * DD * DD + (size_t)e0 * DD + d;
#pragma unroll 4
    for (int e = 0; e < 128; e++) {
        float w = wp[(size_t)e * DD];
#pragma unroll
        for (int b = 0; b < BB; b++) acc[b] = fmaf(sp[b][e], w, acc[b]);
    }
#pragma unroll
    for (int b = 0; b < BB; b++) g_u_part[ec][i][b][d] = acc[b];

    if (dt == 0 && threadIdx.x < BB) {
        int b = threadIdx.x;
        float c = 0.f;
        for (int e = 0; e < 128; e++) c = fmaf(sp[b][e], Vb[i * DD + e0 + e], c);
        g_c_part[ec][i][b] = c;
    }
}

// ---------------- kernel 2: fold u partials -------------------------------
__global__ void k_fold_u() {
    int idx = blockIdx.x * 256 + threadIdx.x;
    if (idx < NLEV * BB * DD) {
        float s = 0.f;
#pragma unroll
        for (int p = 0; p < NECH; p++) s += (&g_u_part[0][0][0][0])[p * NLEV * BB * DD + idx];
        (&g_u[0][0][0])[idx] = s;
    }
}

// ---------------- kernel 3: dots_i[b,t] = enc_hs[b,t,:] . u_i[b,:] --------
// grid (T/32, B), 256 threads. Each warp: 4 rows, 16 front-batched LDG.128.
__global__ void k_dots(const float* __restrict__ enc) {
    int b  = blockIdx.y;
    int t0 = blockIdx.x * 32;

    __shared__ __align__(16) float su[NLEV * DD];
    for (int idx = threadIdx.x; idx < NLEV * DD; idx += 256)
        su[idx] = (&g_u[0][0][0])[(idx / DD) * BB * DD + b * DD + (idx % DD)];
    __syncthreads();

    int warp = threadIdx.x >> 5, lane = threadIdx.x & 31;
    const float4* u0 = (const float4*)(su);
    const float4* u1 = (const float4*)(su + DD);
    const float4* u2 = (const float4*)(su + 2 * DD);
    const float4* e4 = (const float4*)(enc + (size_t)b * TT * DD);
    int tb = t0 + warp * 4;

    // front-batch ALL loads: 16 independent LDG.128 in flight per thread
    float4 h[4][4];
#pragma unroll
    for (int r = 0; r < 4; r++) {
        const float4* row = e4 + (size_t)(tb + r) * (DD / 4) + lane;
#pragma unroll
        for (int q = 0; q < 4; q++) h[r][q] = row[32 * q];
    }

#pragma unroll
    for (int r = 0; r < 4; r++) {
        float a0 = 0.f, a1 = 0.f, a2 = 0.f;
#pragma unroll
        for (int q = 0; q < 4; q++) {
            float4 hh = h[r][q];
            float4 v0 = u0[lane + 32 * q];
            float4 v1 = u1[lane + 32 * q];
            float4 v2 = u2[lane + 32 * q];
            a0 += hh.x * v0.x + hh.y * v0.y + hh.z * v0.z + hh.w * v0.w;
            a1 += hh.x * v1.x + hh.y * v1.y + hh.z * v1.z + hh.w * v1.w;
            a2 += hh.x * v2.x + hh.y * v2.y + hh.z * v2.z + hh.w * v2.w;
        }
#pragma unroll
        for (int off = 16; off; off >>= 1) {
            a0 += __shfl_down_sync(0xFFFFFFFFu, a0, off);
            a1 += __shfl_down_sync(0xFFFFFFFFu, a1, off);
            a2 += __shfl_down_sync(0xFFFFFFFFu, a2, off);
        }
        if (lane == 0) {
            int t = tb + r;
            g_dots[0][b][t] = a0;
            g_dots[1][b][t] = a1;
            g_dots[2][b][t] = a2;
        }
    }
}

// ---------------- kernel 4: window logits + masked softmax + pool weights -
// grid (3, B), 1024 threads. Writes att0 to out and combined weights to g_w.
__global__ void k_softmax(const int* __restrict__ mask, float* __restrict__ out_att) {
    int i = blockIdx.x, b = blockIdx.y;
    int k = i + 1, L = TT - i;
    int tid = threadIdx.x, lane = tid & 31, warp = tid >> 5;

    __shared__ float s[TT];
    __shared__ float red[32];

    const float* dp = &g_dots[i][b][0];
    const int*   mp = mask + b * TT;
    float c = 0.f;
#pragma unroll
    for (int p = 0; p < NECH; p++) c += g_c_part[p][i][b];
    float inv_k = 1.f / (float)k;

    // pass 1: logits + max
    float mx = -INFINITY;
    for (int l = tid; l < TT; l += 1024) {
        float v = -INFINITY;
        if (l < L) {
            float ws = 0.f;
            bool  m  = false;
            for (int j = 0; j < k; j++) { ws += dp[l + j]; m = m || (mp[l + j] != 0); }
            if (!m) v = ws * inv_k + c;
        }
        s[l] = v;
        mx = fmaxf(mx, v);
    }
#pragma unroll
    for (int off = 16; off; off >>= 1) mx = fmaxf(mx, __shfl_down_sync(0xFFFFFFFFu, mx, off));
    if (lane == 0) red[warp] = mx;
    __syncthreads();
    if (warp == 0) {
        float v = red[lane];
#pragma unroll
        for (int off = 16; off; off >>= 1) v = fmaxf(v, __shfl_down_sync(0xFFFFFFFFu, v, off));
        if (lane == 0) red[0] = v;
    }
    __syncthreads();
    mx = red[0];
    __syncthreads();

    // pass 2: exp + sum
    float sum = 0.f;
    for (int l = tid; l < TT; l += 1024) {
        float v = s[l];
        float e = (v == -INFINITY) ? 0.f : __expf(v - mx);
        s[l] = e;
        sum += e;
    }
#pragma unroll
    for (int off = 16; off; off >>= 1) sum += __shfl_down_sync(0xFFFFFFFFu, sum, off);
    if (lane == 0) red[warp] = sum;
    __syncthreads();
    if (warp == 0) {
        float v = red[lane];
#pragma unroll
        for (int off = 16; off; off >>= 1) v += __shfl_down_sync(0xFFFFFFFFu, v, off);
        if (lane == 0) red[0] = v;
    }
    __syncthreads();
    float inv = 1.f / red[0];

    // pass 3: att output (level 0) + combined reverse-window pool weights
    float wscale = inv * inv_k;
    for (int l = tid; l < TT; l += 1024) {
        float e = s[l];
        if (i == 0) out_att[b * TT + l] = e * inv;
        float w = e;
        if (i >= 1 && l >= 1) w += s[l - 1];
        if (i == 2 && l >= 2) w += s[l - 2];
        g_w[i][b][l] = w * wscale;
    }
}

// ---------------- kernel 5: pooled partials (streaming pass 2) ------------
// grid (NPCH, B), 128 threads; each thread owns one float4 column slice.
// chunks in REVERSE order for L2 reuse of enc tail from k_dots.
__global__ void k_pooled(const float* __restrict__ enc) {
    int b     = blockIdx.y;
    int chunk = (NPCH - 1) - blockIdx.x;
    int t0    = chunk * PCH;
    int tid   = threadIdx.x;

    __shared__ float sw[NLEV][PCH];
    for (int idx = tid; idx < NLEV * PCH; idx += 128)
        sw[idx / PCH][idx % PCH] = g_w[idx / PCH][b][t0 + idx % PCH];
    __syncthreads();

    const float4* base = (const float4*)(enc + (size_t)b * TT * DD + (size_t)t0 * DD) + tid;
    float4 a0 = {0,0,0,0}, a1 = {0,0,0,0}, a2 = {0,0,0,0};

#pragma unroll 4
    for (int j = 0; j < PCH; j++) {
        float4 h = base[(size_t)j * (DD / 4)];
        float w0 = sw[0][j], w1 = sw[1][j], w2 = sw[2][j];
        a0.x = fmaf(w0, h.x, a0.x); a0.y = fmaf(w0, h.y, a0.y);
        a0.z = fmaf(w0, h.z, a0.z); a0.w = fmaf(w0, h.w, a0.w);
        a1.x = fmaf(w1, h.x, a1.x); a1.y = fmaf(w1, h.y, a1.y);
        a1.z = fmaf(w1, h.z, a1.z); a1.w = fmaf(w1, h.w, a1.w);
        a2.x = fmaf(w2, h.x, a2.x); a2.y = fmaf(w2, h.y, a2.y);
        a2.z = fmaf(w2, h.z, a2.z); a2.w = fmaf(w2, h.w, a2.w);
    }
    ((float4*)&g_pooled_part[chunk][0][b][0])[tid] = a0;
    ((float4*)&g_pooled_part[chunk][1][b][0])[tid] = a1;
    ((float4*)&g_pooled_part[chunk][2][b][0])[tid] = a2;
}

// ---------------- kernel 6: ctx partials = pooled_i @ Ww[i]^T -------------
// grid (8 dchunks, 4 etiles, 3 levels), 128 threads
__global__ void k_ctx(const float* __restrict__ Ww) {
    int i  = blockIdx.z;
    int e0 = blockIdx.y * 128;
    int dc = blockIdx.x;
    int d0 = dc * 64;

    __shared__ float tW[128 * 65];
    __shared__ float sp[BB * 64];

    for (int idx = threadIdx.x; idx < 128 * 64; idx += 128) {
        int r = idx >> 6, c = idx & 63;
        tW[r * 65 + c] = Ww[(size_t)i * DD * DD + (size_t)(e0 + r) * DD + d0 + c];
    }
    for (int idx = threadIdx.x; idx < BB * 64; idx += 128) {
        int bb = idx >> 6, cc = idx & 63;
        float ssum = 0.f;
#pragma unroll 8
        for (int ch = 0; ch < NPCH; ch++) ssum += g_pooled_part[ch][i][bb][d0 + cc];
        sp[idx] = ssum;
    }
    __syncthreads();

    float acc[BB];
#pragma unroll
    for (int b = 0; b < BB; b++) acc[b] = 0.f;

    for (int c = 0; c < 64; c++) {
        float w = tW[threadIdx.x * 65 + c];
#pragma unroll
        for (int b = 0; b < BB; b++) acc[b] = fmaf(w, sp[b * 64 + c], acc[b]);
    }
    int e = e0 + threadIdx.x;
#pragma unroll
    for (int b = 0; b < BB; b++) g_ctx_part[i][dc][b][e] = acc[b];
}

// ---------------- kernel 7: final ctx fold + bias -> d_out ----------------
__global__ void k_out(const float* __restrict__ Wb, float* __restrict__ out_ctx) {
    int idx = blockIdx.x * 256 + threadIdx.x;  // 0 .. B*D-1
    if (idx >= BB * DD) return;
    int e = idx % DD;
    float s = 0.f;
#pragma unroll
    for (int i = 0; i < NLEV; i++) {
#pragma unroll
        for (int ch = 0; ch < CTXCH; ch++)
            s += (&g_ctx_part[0][0][0][0])[((i * CTXCH + ch) * BB * DD) + idx];
        s += Wb[i * DD + e];
    }
    out_ctx[idx] = s;
}

// ---------------- launch ---------------------------------------------------
extern "C" void kernel_launch(void* const* d_in, const int* in_sizes, int n_in,
                              void* d_out, int out_size) {
    const float* s_prev = (const float*)d_in[0];
    const float* enc    = (const float*)d_in[1];
    const int*   mask   = (const int*)  d_in[2];
    const float* Vw     = (const float*)d_in[3];
    const float* Vb     = (const float*)d_in[4];
    const float* Ww     = (const float*)d_in[5];
    const float* Wb     = (const float*)d_in[6];

    float* out     = (float*)d_out;
    float* out_ctx = out;            // [B, D]
    float* out_att = out + BB * DD;  // [B, T]

    k_proj   <<<dim3(16, NLEV), 128>>>(s_prev, Vw, Vb);
    k_fold_u <<<(NLEV * BB * DD + 255) / 256, 256>>>();
    k_dots   <<<dim3(TT / 32, BB), 256>>>(enc);
    k_softmax<<<dim3(NLEV, BB), 1024>>>(mask, out_att);
    k_pooled <<<dim3(NPCH, BB), 128>>>(enc);
    k_ctx    <<<dim3(CTXCH, 4, NLEV), 128>>>(Ww);
    k_out    <<<(BB * DD + 255) / 256, 256>>>(Wb, out_ctx);
}

// round 5
// speedup vs baseline: 1.5279x; 1.1308x over previous
#include <cuda_runtime.h>
#include <math.h>

#define BB 16
#define TT 4096
#define DD 512
#define NLEV 3
#define NECH 4              // e-chunks in k_proj
#define PCH 64              // tokens per pooled chunk
#define NPCH (TT/PCH)       // 64
#define CTXCH 8             // d-chunks in k_ctx
#define BIG_NEG (-1e30f)

// ---------------- device scratch (no allocations allowed) ----------------
__device__ __align__(16) float g_u_part[NECH][NLEV][BB][DD];
__device__ float g_c_part[NECH][NLEV][BB];
__device__ __align__(16) float g_u[NLEV][BB][DD];
__device__ float g_dots[NLEV][BB][TT];
__device__ float g_w[NLEV][BB][TT];                       // combined pooling weights
__device__ __align__(16) float g_pooled_part[NPCH][NLEV][BB][DD];
__device__ __align__(16) float g_pooled[NLEV][BB][DD];
__device__ float g_ctx_part[NLEV][CTXCH][BB][DD];

// ---------------- kernel 1: u_i = s_prev @ Vw[i], c_i = s_prev . Vb[i] ----
__global__ void k_proj(const float* __restrict__ s_prev,
                       const float* __restrict__ Vw,
                       const float* __restrict__ Vb) {
    int i  = blockIdx.y;
    int dt = blockIdx.x & 3;
    int ec = blockIdx.x >> 2;
    int d  = dt * 128 + threadIdx.x;
    int e0 = ec * 128;

    __shared__ float sp[BB][128];
    for (int idx = threadIdx.x; idx < BB * 128; idx += 128) {
        int b = idx >> 7, e = idx & 127;
        sp[b][e] = s_prev[b * DD + e0 + e];
    }
    __syncthreads();

    float acc[BB];
#pragma unroll
    for (int b = 0; b < BB; b++) acc[b] = 0.f;

    const float* wp = Vw + (size_t)i * DD * DD + (size_t)e0 * DD + d;
#pragma unroll 4
    for (int e = 0; e < 128; e++) {
        float w = wp[(size_t)e * DD];
#pragma unroll
        for (int b = 0; b < BB; b++) acc[b] = fmaf(sp[b][e], w, acc[b]);
    }
#pragma unroll
    for (int b = 0; b < BB; b++) g_u_part[ec][i][b][d] = acc[b];

    if (dt == 0 && threadIdx.x < BB) {
        int b = threadIdx.x;
        float c = 0.f;
        for (int e = 0; e < 128; e++) c = fmaf(sp[b][e], Vb[i * DD + e0 + e], c);
        g_c_part[ec][i][b] = c;
    }
}

// ---------------- kernel 2: fold u partials -------------------------------
__global__ void k_fold_u() {
    int idx = blockIdx.x * 256 + threadIdx.x;
    if (idx < NLEV * BB * DD) {
        float s = 0.f;
#pragma unroll
        for (int p = 0; p < NECH; p++) s += (&g_u_part[0][0][0][0])[p * NLEV * BB * DD + idx];
        (&g_u[0][0][0])[idx] = s;
    }
}

// ---------------- kernel 3: dots_i[b,t] = enc_hs[b,t,:] . u_i[b,:] --------
// grid (T/32, B), 256 threads. Each warp: 4 rows, 16 front-batched LDG.128.
__global__ void __launch_bounds__(256) k_dots(const float* __restrict__ enc) {
    int b  = blockIdx.y;
    int t0 = blockIdx.x * 32;

    __shared__ __align__(16) float su[NLEV * DD];
    for (int idx = threadIdx.x; idx < NLEV * DD; idx += 256)
        su[idx] = (&g_u[0][0][0])[(idx / DD) * BB * DD + b * DD + (idx % DD)];
    __syncthreads();

    int warp = threadIdx.x >> 5, lane = threadIdx.x & 31;
    const float4* u0 = (const float4*)(su);
    const float4* u1 = (const float4*)(su + DD);
    const float4* u2 = (const float4*)(su + 2 * DD);
    const float4* e4 = (const float4*)(enc + (size_t)b * TT * DD);
    int tb = t0 + warp * 4;

    float4 h[4][4];
#pragma unroll
    for (int r = 0; r < 4; r++) {
        const float4* row = e4 + (size_t)(tb + r) * (DD / 4) + lane;
#pragma unroll
        for (int q = 0; q < 4; q++) h[r][q] = row[32 * q];
    }

#pragma unroll
    for (int r = 0; r < 4; r++) {
        float a0 = 0.f, a1 = 0.f, a2 = 0.f;
#pragma unroll
        for (int q = 0; q < 4; q++) {
            float4 hh = h[r][q];
            float4 v0 = u0[lane + 32 * q];
            float4 v1 = u1[lane + 32 * q];
            float4 v2 = u2[lane + 32 * q];
            a0 += hh.x * v0.x + hh.y * v0.y + hh.z * v0.z + hh.w * v0.w;
            a1 += hh.x * v1.x + hh.y * v1.y + hh.z * v1.z + hh.w * v1.w;
            a2 += hh.x * v2.x + hh.y * v2.y + hh.z * v2.z + hh.w * v2.w;
        }
#pragma unroll
        for (int off = 16; off; off >>= 1) {
            a0 += __shfl_down_sync(0xFFFFFFFFu, a0, off);
            a1 += __shfl_down_sync(0xFFFFFFFFu, a1, off);
            a2 += __shfl_down_sync(0xFFFFFFFFu, a2, off);
        }
        if (lane == 0) {
            int t = tb + r;
            g_dots[0][b][t] = a0;
            g_dots[1][b][t] = a1;
            g_dots[2][b][t] = a2;
        }
    }
}

// ---------------- kernel 4: window logits + ONLINE masked softmax ---------
// grid (3, B), 1024 threads. Sentinel BIG_NEG keeps math NaN-free.
__global__ void k_softmax(const int* __restrict__ mask, float* __restrict__ out_att) {
    int i = blockIdx.x, b = blockIdx.y;
    int k = i + 1, L = TT - i;
    int tid = threadIdx.x, lane = tid & 31, warp = tid >> 5;

    __shared__ float s[TT];
    __shared__ float rm[32], rs[32];

    const float* dp = &g_dots[i][b][0];
    const int*   mp = mask + b * TT;
    float c = 0.f;
#pragma unroll
    for (int p = 0; p < NECH; p++) c += g_c_part[p][i][b];
    float inv_k = 1.f / (float)k;

    // pass 1: logits + online (m, s)
    float m = BIG_NEG, sum = 0.f;
    for (int l = tid; l < TT; l += 1024) {
        float v = BIG_NEG;
        if (l < L) {
            float ws = 0.f;
            bool  mk = false;
            for (int j = 0; j < k; j++) { ws += dp[l + j]; mk = mk || (mp[l + j] != 0); }
            if (!mk) v = ws * inv_k + c;
        }
        s[l] = v;
        if (v > m) { sum = sum * __expf(m - v) + 1.f; m = v; }
        else       { sum += __expf(v - m); }
    }
    // warp combine
#pragma unroll
    for (int off = 16; off; off >>= 1) {
        float m2 = __shfl_xor_sync(0xFFFFFFFFu, m, off);
        float s2 = __shfl_xor_sync(0xFFFFFFFFu, sum, off);
        float M  = fmaxf(m, m2);
        sum = sum * __expf(m - M) + s2 * __expf(m2 - M);
        m = M;
    }
    if (lane == 0) { rm[warp] = m; rs[warp] = sum; }
    __syncthreads();
    if (warp == 0) {
        float mm = rm[lane], ss = rs[lane];
#pragma unroll
        for (int off = 16; off; off >>= 1) {
            float m2 = __shfl_xor_sync(0xFFFFFFFFu, mm, off);
            float s2 = __shfl_xor_sync(0xFFFFFFFFu, ss, off);
            float M  = fmaxf(mm, m2);
            ss = ss * __expf(mm - M) + s2 * __expf(m2 - M);
            mm = M;
        }
        if (lane == 0) { rm[0] = mm; rs[0] = ss; }
    }
    __syncthreads();
    float M   = rm[0];
    float inv = 1.f / rs[0];

    // pass 2: outputs (recompute neighbor exps from logits; no extra barrier)
    float wscale = inv * inv_k;
    for (int l = tid; l < TT; l += 1024) {
        float e0 = __expf(s[l] - M);
        if (i == 0) out_att[b * TT + l] = e0 * inv;
        float w = e0;
        if (i >= 1 && l >= 1) w += __expf(s[l - 1] - M);
        if (i == 2 && l >= 2) w += __expf(s[l - 2] - M);
        g_w[i][b][l] = w * wscale;
    }
}

// ---------------- kernel 5: pooled partials (streaming pass 2) ------------
// grid (NPCH, B), 128 threads. BOTH batch and chunk reversed so this pass
// begins exactly where k_dots ended (L2 reuse: enc=128MB vs L2=126MB).
__global__ void k_pooled(const float* __restrict__ enc) {
    int b     = (BB - 1) - blockIdx.y;
    int chunk = (NPCH - 1) - blockIdx.x;
    int t0    = chunk * PCH;
    int tid   = threadIdx.x;

    __shared__ float sw[NLEV][PCH];
    for (int idx = tid; idx < NLEV * PCH; idx += 128)
        sw[idx / PCH][idx % PCH] = g_w[idx / PCH][b][t0 + idx % PCH];
    __syncthreads();

    const float4* base = (const float4*)(enc + (size_t)b * TT * DD + (size_t)t0 * DD) + tid;
    float4 a0 = {0,0,0,0}, a1 = {0,0,0,0}, a2 = {0,0,0,0};

#pragma unroll 8
    for (int j = 0; j < PCH; j++) {
        float4 h = base[(size_t)j * (DD / 4)];
        float w0 = sw[0][j], w1 = sw[1][j], w2 = sw[2][j];
        a0.x = fmaf(w0, h.x, a0.x); a0.y = fmaf(w0, h.y, a0.y);
        a0.z = fmaf(w0, h.z, a0.z); a0.w = fmaf(w0, h.w, a0.w);
        a1.x = fmaf(w1, h.x, a1.x); a1.y = fmaf(w1, h.y, a1.y);
        a1.z = fmaf(w1, h.z, a1.z); a1.w = fmaf(w1, h.w, a1.w);
        a2.x = fmaf(w2, h.x, a2.x); a2.y = fmaf(w2, h.y, a2.y);
        a2.z = fmaf(w2, h.z, a2.z); a2.w = fmaf(w2, h.w, a2.w);
    }
    ((float4*)&g_pooled_part[chunk][0][b][0])[tid] = a0;
    ((float4*)&g_pooled_part[chunk][1][b][0])[tid] = a1;
    ((float4*)&g_pooled_part[chunk][2][b][0])[tid] = a2;
}

// ---------------- kernel 5b: fold pooled partials (once) ------------------
__global__ void k_fold_pooled() {
    int idx = blockIdx.x * 256 + threadIdx.x;   // < NLEV*BB*DD = 24576
    if (idx >= NLEV * BB * DD) return;
    float s = 0.f;
#pragma unroll 8
    for (int ch = 0; ch < NPCH; ch++)
        s += (&g_pooled_part[0][0][0][0])[(size_t)ch * NLEV * BB * DD + idx];
    (&g_pooled[0][0][0])[idx] = s;
}

// ---------------- kernel 6: ctx partials = pooled_i @ Ww[i]^T -------------
__global__ void k_ctx(const float* __restrict__ Ww) {
    int i  = blockIdx.z;
    int e0 = blockIdx.y * 128;
    int dc = blockIdx.x;
    int d0 = dc * 64;

    __shared__ float tW[128 * 65];
    __shared__ float sp[BB * 64];

    for (int idx = threadIdx.x; idx < 128 * 64; idx += 128) {
        int r = idx >> 6, c = idx & 63;
        tW[r * 65 + c] = Ww[(size_t)i * DD * DD + (size_t)(e0 + r) * DD + d0 + c];
    }
    for (int idx = threadIdx.x; idx < BB * 64; idx += 128) {
        int bb = idx >> 6, cc = idx & 63;
        sp[idx] = g_pooled[i][bb][d0 + cc];
    }
    __syncthreads();

    float acc[BB];
#pragma unroll
    for (int b = 0; b < BB; b++) acc[b] = 0.f;

    for (int c = 0; c < 64; c++) {
        float w = tW[threadIdx.x * 65 + c];
#pragma unroll
        for (int b = 0; b < BB; b++) acc[b] = fmaf(w, sp[b * 64 + c], acc[b]);
    }
    int e = e0 + threadIdx.x;
#pragma unroll
    for (int b = 0; b < BB; b++) g_ctx_part[i][dc][b][e] = acc[b];
}

// ---------------- kernel 7: final ctx fold + bias -> d_out ----------------
__global__ void k_out(const float* __restrict__ Wb, float* __restrict__ out_ctx) {
    int idx = blockIdx.x * 256 + threadIdx.x;   // 0 .. B*D-1
    if (idx >= BB * DD) return;
    int e = idx % DD;
    float s = 0.f;
#pragma unroll
    for (int i = 0; i < NLEV; i++) {
#pragma unroll
        for (int ch = 0; ch < CTXCH; ch++)
            s += (&g_ctx_part[0][0][0][0])[((i * CTXCH + ch) * BB * DD) + idx];
        s += Wb[i * DD + e];
    }
    out_ctx[idx] = s;
}

// ---------------- launch ---------------------------------------------------
extern "C" void kernel_launch(void* const* d_in, const int* in_sizes, int n_in,
                              void* d_out, int out_size) {
    const float* s_prev = (const float*)d_in[0];
    const float* enc    = (const float*)d_in[1];
    const int*   mask   = (const int*)  d_in[2];
    const float* Vw     = (const float*)d_in[3];
    const float* Vb     = (const float*)d_in[4];
    const float* Ww     = (const float*)d_in[5];
    const float* Wb     = (const float*)d_in[6];

    float* out     = (float*)d_out;
    float* out_ctx = out;            // [B, D]
    float* out_att = out + BB * DD;  // [B, T]

    k_proj       <<<dim3(16, NLEV), 128>>>(s_prev, Vw, Vb);
    k_fold_u     <<<(NLEV * BB * DD + 255) / 256, 256>>>();
    k_dots       <<<dim3(TT / 32, BB), 256>>>(enc);
    k_softmax    <<<dim3(NLEV, BB), 1024>>>(mask, out_att);
    k_pooled     <<<dim3(NPCH, BB), 128>>>(enc);
    k_fold_pooled<<<(NLEV * BB * DD + 255) / 256, 256>>>();
    k_ctx        <<<dim3(CTXCH, 4, NLEV), 128>>>(Ww);
    k_out        <<<(BB * DD + 255) / 256, 256>>>(Wb, out_ctx);
}